// round 7
// baseline (speedup 1.0000x reference)
#include <cuda_runtime.h>

#define N_MAX   1000000
#define D       32
#define HID     16
#define NB      592          // 148 SMs x 4 blocks
#define T1      128

// ---------------- scratch (no allocations allowed) ----------------
__device__ float g_a[N_MAX];          // per-row raw attention logits
__device__ float g_bs[NB];            // per-block sum of exp(a)
__device__ float g_bB[NB * D];        // per-block partial sum alpha*H
__device__ float g_invS;              // 1 / sum exp(a)
__device__ unsigned int g_cnt1;       // zero-init; reset each replay
__device__ unsigned int g_cnt3;

// ---------------- packed f32x2 helpers ----------------
__device__ __forceinline__ unsigned long long pack2(float lo, float hi) {
    unsigned long long r;
    asm("mov.b64 %0, {%1, %2};" : "=l"(r) : "f"(lo), "f"(hi));
    return r;
}
__device__ __forceinline__ void unpack2(unsigned long long v, float& lo, float& hi) {
    asm("mov.b64 {%0, %1}, %2;" : "=f"(lo), "=f"(hi) : "l"(v));
}
__device__ __forceinline__ void fma2(unsigned long long& d,
                                     unsigned long long a, unsigned long long b) {
    asm("fma.rn.f32x2 %0, %1, %2, %3;" : "=l"(d) : "l"(a), "l"(b), "l"(d));
}
__device__ __forceinline__ float fast_tanh(float x) {
    float r;
    asm("tanh.approx.f32 %0, %1;" : "=f"(r) : "f"(x));
    return r;
}

// =====================================================================
// K1: logits ONLY (no B accumulator — R1/R6 proved v/u + B together
// exceed the 255-reg file and spill; R3-K3 proved each half alone fits).
//   a_i -> g_a ;  s += exp(a_i)   (unshifted exp safe: |a| <~ 10)
// Front-batched 8x LDG.128 (MLP=8; R3 measured MLP=1 costs 10x).
// No occupancy clause (R2 measured the reg cap forces spills).
// Last finishing block reduces S -> g_invS.
// =====================================================================
__global__ void __launch_bounds__(T1)
k1_logits(const float4* __restrict__ H4, int n,
          const float* __restrict__ Wv, const float* __restrict__ bv,
          const float* __restrict__ Wu, const float* __restrict__ bu,
          const float* __restrict__ Ww, const float* __restrict__ bw)
{
    // sw[d][0..15] = Wv[d][:],  sw[d][16..31] = Wu[d][:]
    __shared__ __align__(16) float sw[D][32];
    __shared__ float sbv[HID], sbu[HID], sWw[HID];
    __shared__ float red_s[T1];
    __shared__ bool  isLast;

    const int t = threadIdx.x;
    for (int i = t; i < D * HID; i += T1) {
        sw[i / HID][i % HID]      = Wv[i];
        sw[i / HID][16 + i % HID] = Wu[i];
    }
    if (t < HID) { sbv[t] = bv[t]; sbu[t] = bu[t]; sWw[t] = Ww[t]; }
    __syncthreads();

    const float bw0 = bw[0];
    float s = 0.0f;

    #pragma unroll 1
    for (int r = blockIdx.x * T1 + t; r < n; r += NB * T1) {
        // ---- front-batched row load: 8 independent LDG.128 ----
        const float4* p = H4 + (size_t)r * 8;
        float4 x[8];
        #pragma unroll
        for (int c = 0; c < 8; c++) x[c] = p[c];

        unsigned long long v[HID / 2], u[HID / 2];
        #pragma unroll
        for (int k = 0; k < HID / 2; k++) { v[k] = 0ULL; u[k] = 0ULL; }

        #pragma unroll
        for (int c = 0; c < 8; c++) {
            #pragma unroll
            for (int j = 0; j < 4; j++) {
                const float xj = (j == 0) ? x[c].x : (j == 1) ? x[c].y
                               : (j == 2) ? x[c].z : x[c].w;
                const unsigned long long hd = pack2(xj, xj);
                const ulonglong2* w2 = (const ulonglong2*)sw[c * 4 + j];
                #pragma unroll
                for (int k = 0; k < 4; k++) {          // Wv half
                    ulonglong2 w = w2[k];
                    fma2(v[2 * k], hd, w.x);
                    fma2(v[2 * k + 1], hd, w.y);
                }
                #pragma unroll
                for (int k = 0; k < 4; k++) {          // Wu half
                    ulonglong2 w = w2[4 + k];
                    fma2(u[2 * k], hd, w.x);
                    fma2(u[2 * k + 1], hd, w.y);
                }
            }
        }

        float a = bw0;
        #pragma unroll
        for (int k = 0; k < HID / 2; k++) {
            float v0, v1, u0, u1;
            unpack2(v[k], v0, v1);
            unpack2(u[k], u0, u1);
            const int h0 = 2 * k, h1 = 2 * k + 1;
            float t0 = fast_tanh(v0 + sbv[h0]);
            float t1 = fast_tanh(v1 + sbv[h1]);
            float s0 = fmaf(0.5f, fast_tanh(0.5f * (u0 + sbu[h0])), 0.5f);
            float s1 = fmaf(0.5f, fast_tanh(0.5f * (u1 + sbu[h1])), 0.5f);
            a = fmaf(sWw[h0] * t0, s0, a);
            a = fmaf(sWw[h1] * t1, s1, a);
        }
        g_a[r] = a;
        s += __expf(a);
    }

    // ---- block reduction of s ----
    red_s[t] = s;
    for (int stride = T1 / 2; stride >= 1; stride >>= 1) {
        __syncthreads();
        if (t < stride) red_s[t] += red_s[t + stride];
    }
    __syncthreads();
    if (t == 0) g_bs[blockIdx.x] = red_s[0];

    // ---- last finishing block: S -> invS ----
    __threadfence();
    if (t == 0) isLast = (atomicAdd(&g_cnt1, 1u) == NB - 1);
    __syncthreads();
    if (!isLast) return;

    float ls = 0.0f;
    for (int b = t; b < NB; b += T1) ls += g_bs[b];
    red_s[t] = ls;
    for (int stride = T1 / 2; stride >= 1; stride >>= 1) {
        __syncthreads();
        if (t < stride) red_s[t] += red_s[t + stride];
    }
    __syncthreads();
    if (t == 0) {
        g_invS = 1.0f / red_s[0];
        g_cnt1 = 0;                            // reset for next graph replay
        __threadfence();
    }
}

// =====================================================================
// K3: alpha_i = exp(a_i)*invS (written out) + per-block partial
//     B = sum alpha_i * H_i  (this exact loop measured 42us/76regs in R3)
// Last finishing block: Bbar (+already normalized) + score head.
// =====================================================================
__global__ void __launch_bounds__(T1)
k3_alpha_B(const float4* __restrict__ H4, int n, float* __restrict__ alpha,
           const float* __restrict__ TPL,
           const float* __restrict__ W1, const float* __restrict__ b1,
           const float* __restrict__ W2, const float* __restrict__ b2,
           float* __restrict__ out_score)
{
    __shared__ float redB[T1][D];       // 16 KB
    __shared__ bool  isLast;
    const int t = threadIdx.x;
    const float invS = g_invS;

    unsigned long long B[D / 2];
    #pragma unroll
    for (int k = 0; k < D / 2; k++) B[k] = 0ULL;

    #pragma unroll 1
    for (int r = blockIdx.x * T1 + t; r < n; r += NB * T1) {
        const float4* p = H4 + (size_t)r * 8;
        float4 x[8];
        #pragma unroll
        for (int c = 0; c < 8; c++) x[c] = p[c];

        float e = __expf(g_a[r]) * invS;
        alpha[r] = e;

        const unsigned long long ee = pack2(e, e);
        #pragma unroll
        for (int c = 0; c < 8; c++) {
            fma2(B[2 * c],     ee, pack2(x[c].x, x[c].y));
            fma2(B[2 * c + 1], ee, pack2(x[c].z, x[c].w));
        }
    }

    #pragma unroll
    for (int k = 0; k < D / 2; k++) {
        float lo, hi;
        unpack2(B[k], lo, hi);
        redB[t][2 * k] = lo; redB[t][2 * k + 1] = hi;
    }
    __syncthreads();
    if (t < D) {
        float acc = 0.0f;
        #pragma unroll 8
        for (int i = 0; i < T1; i++) acc += redB[i][t];
        g_bB[blockIdx.x * D + t] = acc;
    }

    // ---- last finishing block: Bbar + score head ----
    __threadfence();
    if (t == 0) isLast = (atomicAdd(&g_cnt3, 1u) == NB - 1);
    __syncthreads();
    if (!isLast) return;

    {
        const int d = t & (D - 1);
        const int g = t >> 5;               // 0..3
        float acc = 0.0f;
        for (int b = g; b < NB; b += 4) acc += g_bB[b * D + d];
        redB[g][d] = acc;
    }
    __syncthreads();

    __shared__ float Bbar[D];
    __shared__ float hsh[HID];
    if (t < D) Bbar[t] = redB[0][t] + redB[1][t] + redB[2][t] + redB[3][t];
    __syncthreads();
    if (t < HID) {
        float a3 = b1[t] + TPL[0] * W1[D * HID + t];   // W1 row 32 = TPL row
        #pragma unroll
        for (int dd = 0; dd < D; dd++) a3 = fmaf(Bbar[dd], W1[dd * HID + t], a3);
        hsh[t] = fmaxf(a3, 0.0f);
    }
    __syncthreads();
    if (t == 0) {
        float sc = b2[0];
        #pragma unroll
        for (int j = 0; j < HID; j++) sc = fmaf(hsh[j], W2[j], sc);
        out_score[0] = sc;
        g_cnt3 = 0;                         // reset for next graph replay
        __threadfence();
    }
}

// =====================================================================
// Inputs (metadata order): H, TPL, Wv, bv, Wu, bu, Ww, bw, W1, b1, W2, b2
// Output: [score, alpha[0..N-1]]
// =====================================================================
extern "C" void kernel_launch(void* const* d_in, const int* in_sizes, int n_in,
                              void* d_out, int out_size)
{
    const float* H   = (const float*)d_in[0];
    const float* TPL = (const float*)d_in[1];
    const float* Wv  = (const float*)d_in[2];
    const float* bv  = (const float*)d_in[3];
    const float* Wu  = (const float*)d_in[4];
    const float* bu  = (const float*)d_in[5];
    const float* Ww  = (const float*)d_in[6];
    const float* bw  = (const float*)d_in[7];
    const float* W1  = (const float*)d_in[8];
    const float* b1  = (const float*)d_in[9];
    const float* W2  = (const float*)d_in[10];
    const float* b2  = (const float*)d_in[11];
    float* out = (float*)d_out;

    const int n = in_sizes[0] / D;   // 1,000,000

    k1_logits<<<NB, T1>>>((const float4*)H, n, Wv, bv, Wu, bu, Ww, bw);
    k3_alpha_B<<<NB, T1>>>((const float4*)H, n, out + 1,
                           TPL, W1, b1, W2, b2, out);
}

// round 8
// speedup vs baseline: 1.1714x; 1.1714x over previous
#include <cuda_runtime.h>

#define N_MAX   1000000
#define D       32
#define HID     16
#define NB      592          // 148 SMs x 4 blocks
#define T1      128

// ---------------- scratch (no allocations allowed) ----------------
__device__ float g_a[N_MAX];          // per-row raw attention logits
__device__ float g_bs[NB];            // per-block sum of exp(a)
__device__ float g_bB[NB * D];        // per-block partial sum alpha*H
__device__ float g_invS;              // 1 / sum exp(a)
__device__ unsigned int g_cnt1;       // zero-init; reset each replay
__device__ unsigned int g_cnt3;

// ---------------- helpers ----------------
__device__ __forceinline__ unsigned long long pack2(float lo, float hi) {
    unsigned long long r;
    asm("mov.b64 %0, {%1, %2};" : "=l"(r) : "f"(lo), "f"(hi));
    return r;
}
__device__ __forceinline__ void unpack2(unsigned long long v, float& lo, float& hi) {
    asm("mov.b64 {%0, %1}, %2;" : "=f"(lo), "=f"(hi) : "l"(v));
}
__device__ __forceinline__ void fma2(unsigned long long& d,
                                     unsigned long long a, unsigned long long b) {
    asm("fma.rn.f32x2 %0, %1, %2, %3;" : "=l"(d) : "l"(a), "l"(b), "l"(d));
}
__device__ __forceinline__ float fast_tanh(float x) {
    float r;
    asm("tanh.approx.f32 %0, %1;" : "=f"(r) : "f"(x));
    return r;
}

// =====================================================================
// K1: logits + sum(exp).  PLAIN SCALAR matvec — the packed f32x2
// inline-asm ("=l"/"l" 64-bit constraints) is the measured common
// factor in every 800-1500us variant; scalar fmaf + float4 LDS is the
// form ptxas pipelines properly.
// Front-batched 8x LDG.128 (R3: MLP=1 costs 10x). No occupancy clause
// (R2: reg caps force spills). Unshifted exp safe: |a| <= ~10.
// =====================================================================
__global__ void __launch_bounds__(T1)
k1_logits(const float4* __restrict__ H4, int n,
          const float* __restrict__ Wv, const float* __restrict__ bv,
          const float* __restrict__ Wu, const float* __restrict__ bu,
          const float* __restrict__ Ww, const float* __restrict__ bw)
{
    __shared__ __align__(16) float swv[D][HID];   // Wv row-major
    __shared__ __align__(16) float swu[D][HID];   // Wu row-major
    __shared__ float sbv[HID], sbu[HID], sWw[HID];
    __shared__ float red_s[T1];
    __shared__ bool  isLast;

    const int t = threadIdx.x;
    for (int i = t; i < D * HID; i += T1) {
        swv[i / HID][i % HID] = Wv[i];
        swu[i / HID][i % HID] = Wu[i];
    }
    if (t < HID) { sbv[t] = bv[t]; sbu[t] = bu[t]; sWw[t] = Ww[t]; }
    __syncthreads();

    const float bw0 = bw[0];
    float s = 0.0f;

    #pragma unroll 1
    for (int r = blockIdx.x * T1 + t; r < n; r += NB * T1) {
        // ---- front-batched row load: 8 independent LDG.128 ----
        const float4* p = H4 + (size_t)r * 8;
        float4 x[8];
        #pragma unroll
        for (int c = 0; c < 8; c++) x[c] = p[c];

        float v[HID], u[HID];
        #pragma unroll
        for (int h = 0; h < HID; h++) { v[h] = 0.0f; u[h] = 0.0f; }

        #pragma unroll
        for (int c = 0; c < 8; c++) {
            float xs[4] = {x[c].x, x[c].y, x[c].z, x[c].w};
            #pragma unroll
            for (int j = 0; j < 4; j++) {
                const int d = c * 4 + j;
                const float xd = xs[j];
                const float4* wv4 = (const float4*)swv[d];
                const float4* wu4 = (const float4*)swu[d];
                #pragma unroll
                for (int q = 0; q < 4; q++) {
                    float4 w = wv4[q];
                    v[4 * q + 0] = fmaf(xd, w.x, v[4 * q + 0]);
                    v[4 * q + 1] = fmaf(xd, w.y, v[4 * q + 1]);
                    v[4 * q + 2] = fmaf(xd, w.z, v[4 * q + 2]);
                    v[4 * q + 3] = fmaf(xd, w.w, v[4 * q + 3]);
                }
                #pragma unroll
                for (int q = 0; q < 4; q++) {
                    float4 w = wu4[q];
                    u[4 * q + 0] = fmaf(xd, w.x, u[4 * q + 0]);
                    u[4 * q + 1] = fmaf(xd, w.y, u[4 * q + 1]);
                    u[4 * q + 2] = fmaf(xd, w.z, u[4 * q + 2]);
                    u[4 * q + 3] = fmaf(xd, w.w, u[4 * q + 3]);
                }
            }
        }

        float a = bw0;
        #pragma unroll
        for (int h = 0; h < HID; h++) {
            float th = fast_tanh(v[h] + sbv[h]);
            float sg = fmaf(0.5f, fast_tanh(0.5f * (u[h] + sbu[h])), 0.5f);
            a = fmaf(sWw[h] * th, sg, a);
        }
        g_a[r] = a;
        s += __expf(a);
    }

    // ---- block reduction of s ----
    red_s[t] = s;
    for (int stride = T1 / 2; stride >= 1; stride >>= 1) {
        __syncthreads();
        if (t < stride) red_s[t] += red_s[t + stride];
    }
    __syncthreads();
    if (t == 0) g_bs[blockIdx.x] = red_s[0];

    // ---- last finishing block: S -> invS ----
    __threadfence();
    if (t == 0) isLast = (atomicAdd(&g_cnt1, 1u) == NB - 1);
    __syncthreads();
    if (!isLast) return;

    float ls = 0.0f;
    for (int b = t; b < NB; b += T1) ls += g_bs[b];
    red_s[t] = ls;
    for (int stride = T1 / 2; stride >= 1; stride >>= 1) {
        __syncthreads();
        if (t < stride) red_s[t] += red_s[t + stride];
    }
    __syncthreads();
    if (t == 0) {
        g_invS = 1.0f / red_s[0];
        g_cnt1 = 0;                            // reset for next graph replay
        __threadfence();
    }
}

// =====================================================================
// K3: alpha_i = exp(a_i)*invS (written out) + per-block partial
//     B = sum alpha_i * H_i   — byte-identical to the 42us/56reg
//     kernel measured in R3 and R7. Last block: Bbar + score head.
// =====================================================================
__global__ void __launch_bounds__(T1)
k3_alpha_B(const float4* __restrict__ H4, int n, float* __restrict__ alpha,
           const float* __restrict__ TPL,
           const float* __restrict__ W1, const float* __restrict__ b1,
           const float* __restrict__ W2, const float* __restrict__ b2,
           float* __restrict__ out_score)
{
    __shared__ float redB[T1][D];       // 16 KB
    __shared__ bool  isLast;
    const int t = threadIdx.x;
    const float invS = g_invS;

    unsigned long long B[D / 2];
    #pragma unroll
    for (int k = 0; k < D / 2; k++) B[k] = 0ULL;

    #pragma unroll 1
    for (int r = blockIdx.x * T1 + t; r < n; r += NB * T1) {
        const float4* p = H4 + (size_t)r * 8;
        float4 x[8];
        #pragma unroll
        for (int c = 0; c < 8; c++) x[c] = p[c];

        float e = __expf(g_a[r]) * invS;
        alpha[r] = e;

        const unsigned long long ee = pack2(e, e);
        #pragma unroll
        for (int c = 0; c < 8; c++) {
            fma2(B[2 * c],     ee, pack2(x[c].x, x[c].y));
            fma2(B[2 * c + 1], ee, pack2(x[c].z, x[c].w));
        }
    }

    #pragma unroll
    for (int k = 0; k < D / 2; k++) {
        float lo, hi;
        unpack2(B[k], lo, hi);
        redB[t][2 * k] = lo; redB[t][2 * k + 1] = hi;
    }
    __syncthreads();
    if (t < D) {
        float acc = 0.0f;
        #pragma unroll 8
        for (int i = 0; i < T1; i++) acc += redB[i][t];
        g_bB[blockIdx.x * D + t] = acc;
    }

    // ---- last finishing block: Bbar + score head ----
    __threadfence();
    if (t == 0) isLast = (atomicAdd(&g_cnt3, 1u) == NB - 1);
    __syncthreads();
    if (!isLast) return;

    {
        const int d = t & (D - 1);
        const int g = t >> 5;               // 0..3
        float acc = 0.0f;
        for (int b = g; b < NB; b += 4) acc += g_bB[b * D + d];
        redB[g][d] = acc;
    }
    __syncthreads();

    __shared__ float Bbar[D];
    __shared__ float hsh[HID];
    if (t < D) Bbar[t] = redB[0][t] + redB[1][t] + redB[2][t] + redB[3][t];
    __syncthreads();
    if (t < HID) {
        float a3 = b1[t] + TPL[0] * W1[D * HID + t];   // W1 row 32 = TPL row
        #pragma unroll
        for (int dd = 0; dd < D; dd++) a3 = fmaf(Bbar[dd], W1[dd * HID + t], a3);
        hsh[t] = fmaxf(a3, 0.0f);
    }
    __syncthreads();
    if (t == 0) {
        float sc = b2[0];
        #pragma unroll
        for (int j = 0; j < HID; j++) sc = fmaf(hsh[j], W2[j], sc);
        out_score[0] = sc;
        g_cnt3 = 0;                         // reset for next graph replay
        __threadfence();
    }
}

// =====================================================================
// Inputs (metadata order): H, TPL, Wv, bv, Wu, bu, Ww, bw, W1, b1, W2, b2
// Output: [score, alpha[0..N-1]]
// =====================================================================
extern "C" void kernel_launch(void* const* d_in, const int* in_sizes, int n_in,
                              void* d_out, int out_size)
{
    const float* H   = (const float*)d_in[0];
    const float* TPL = (const float*)d_in[1];
    const float* Wv  = (const float*)d_in[2];
    const float* bv  = (const float*)d_in[3];
    const float* Wu  = (const float*)d_in[4];
    const float* bu  = (const float*)d_in[5];
    const float* Ww  = (const float*)d_in[6];
    const float* bw  = (const float*)d_in[7];
    const float* W1  = (const float*)d_in[8];
    const float* b1  = (const float*)d_in[9];
    const float* W2  = (const float*)d_in[10];
    const float* b2  = (const float*)d_in[11];
    float* out = (float*)d_out;

    const int n = in_sizes[0] / D;   // 1,000,000

    k1_logits<<<NB, T1>>>((const float4*)H, n, Wv, bv, Wu, bu, Ww, bw);
    k3_alpha_B<<<NB, T1>>>((const float4*)H, n, out + 1,
                           TPL, W1, b1, W2, b2, out);
}

// round 9
// speedup vs baseline: 4.4654x; 3.8120x over previous
#include <cuda_runtime.h>

#define N_MAX   1000000
#define D       32
#define HID     16
#define NB      592          // 148 SMs x 4 blocks
#define T1      128
#define TR      128          // H-tile rows per block

// ---------------- scratch (no allocations allowed) ----------------
__device__ float g_a[N_MAX];          // per-row raw attention logits
__device__ float g_bs[NB];            // per-block sum of exp(a)
__device__ float g_bB[NB * D];        // per-block partial sum alpha*H
__device__ float g_invS;              // 1 / sum exp(a)
__device__ unsigned int g_cnt1;       // zero-init; reset each replay
__device__ unsigned int g_cnt3;
__device__ float g_dummy;             // dummy-kernel sink

// ---------------- helpers ----------------
__device__ __forceinline__ unsigned long long pack2(float lo, float hi) {
    unsigned long long r;
    asm("mov.b64 %0, {%1, %2};" : "=l"(r) : "f"(lo), "f"(hi));
    return r;
}
__device__ __forceinline__ void unpack2(unsigned long long v, float& lo, float& hi) {
    asm("mov.b64 {%0, %1}, %2;" : "=f"(lo), "=f"(hi) : "l"(v));
}
__device__ __forceinline__ void fma2(unsigned long long& d,
                                     unsigned long long a, unsigned long long b) {
    asm("fma.rn.f32x2 %0, %1, %2, %3;" : "=l"(d) : "l"(a), "l"(b), "l"(d));
}
__device__ __forceinline__ float fast_tanh(float x) {
    float r;
    asm("tanh.approx.f32 %0, %1;" : "=f"(r) : "f"(x));
    return r;
}

// =====================================================================
// K1 (tiled): logits + sum(exp).
//  - H tile (128x32) staged in shared via COALESCED LDG.128
//  - weights live in per-lane REGISTERS: lane l<16 -> Wv[:,l],
//    lane l>=16 -> Wu[:,l-16]  (zero inner-loop weight loads)
//  - warp-per-row-pair: broadcast LDS.128 of row + register FFMAs
//  - epilogue: one shfl_xor(16) pairs tanh/sigmoid halves; 4-shfl
//    butterfly reduces the Ww-weighted sum
// This removes the shared-weight broadcast matvec that every slow K1
// (R1,R3,R6,R7,R8: 770-1360us vs 60us floor) had in common.
// =====================================================================
__global__ void __launch_bounds__(T1)
k1_tiled(const float4* __restrict__ H4, int n,
         const float* __restrict__ Wv, const float* __restrict__ bv,
         const float* __restrict__ Wu, const float* __restrict__ bu,
         const float* __restrict__ Ww, const float* __restrict__ bw)
{
    __shared__ __align__(16) float4 sH[TR][8];     // 16 KB
    __shared__ float sWv[D * HID], sWu[D * HID];   // 4 KB staging
    __shared__ float red_s[T1];
    __shared__ bool  isLast;

    const int t = threadIdx.x;
    const int w = t >> 5;              // warp 0..3
    const int l = t & 31;              // lane

    for (int i = t; i < D * HID; i += T1) { sWv[i] = Wv[i]; sWu[i] = Wu[i]; }
    __syncthreads();

    // per-lane weight column in registers
    float Wreg[D];
    const bool isV = (l < HID);
    const int  h   = isV ? l : (l - HID);
    #pragma unroll
    for (int d = 0; d < D; d++)
        Wreg[d] = isV ? sWv[d * HID + h] : sWu[d * HID + h];

    const float bias  = isV ? bv[h] : bu[h];
    const float prem  = isV ? 1.0f : 0.5f;    // arg scale  (sigmoid via tanh)
    const float postm = isV ? 1.0f : 0.5f;    // act = postm*tanh + postb
    const float postb = isV ? 0.0f : 0.5f;
    const float wwl   = isV ? Ww[h] : 0.0f;   // only V-lanes carry Ww
    const float bw0   = bw[0];

    float s = 0.0f;

    for (int base = blockIdx.x * TR; base < n; base += NB * TR) {
        const int rows = min(TR, n - base);
        __syncthreads();                       // sH reuse guard
        for (int f = t; f < rows * 8; f += T1)
            ((float4*)sH)[f] = H4[(size_t)base * 8 + f];
        __syncthreads();

        // warp w owns tile rows [w*32, w*32+32)
        for (int i = 0; i < 32; i += 2) {
            const int r0 = w * 32 + i;
            if (r0 >= rows) break;             // warp-uniform

            float acc0 = 0.0f, acc1 = 0.0f;
            #pragma unroll
            for (int q = 0; q < 8; q++) {
                float4 x0 = sH[r0][q];         // broadcast LDS.128
                float4 x1 = sH[r0 + 1][q];
                acc0 = fmaf(x0.x, Wreg[4 * q + 0], acc0);
                acc0 = fmaf(x0.y, Wreg[4 * q + 1], acc0);
                acc0 = fmaf(x0.z, Wreg[4 * q + 2], acc0);
                acc0 = fmaf(x0.w, Wreg[4 * q + 3], acc0);
                acc1 = fmaf(x1.x, Wreg[4 * q + 0], acc1);
                acc1 = fmaf(x1.y, Wreg[4 * q + 1], acc1);
                acc1 = fmaf(x1.z, Wreg[4 * q + 2], acc1);
                acc1 = fmaf(x1.w, Wreg[4 * q + 3], acc1);
            }

            #pragma unroll
            for (int p = 0; p < 2; p++) {
                const int   rr  = r0 + p;
                const float acc = p ? acc1 : acc0;
                // activation (V: tanh, U: sigmoid via tanh) with lane consts
                float act = fmaf(postm, fast_tanh(prem * (acc + bias)), postb);
                float par = __shfl_xor_sync(0xffffffffu, act, 16);
                float c   = wwl * act * par;           // 0 on U-lanes
                c += __shfl_xor_sync(0xffffffffu, c, 8);
                c += __shfl_xor_sync(0xffffffffu, c, 4);
                c += __shfl_xor_sync(0xffffffffu, c, 2);
                c += __shfl_xor_sync(0xffffffffu, c, 1);
                if (rr < rows && l == 0) {
                    const float a = c + bw0;
                    g_a[base + rr] = a;
                    s += __expf(a);
                }
            }
        }
    }

    // ---- block reduction of s (only lane0s carry nonzero) ----
    __syncthreads();
    red_s[t] = s;
    for (int stride = T1 / 2; stride >= 1; stride >>= 1) {
        __syncthreads();
        if (t < stride) red_s[t] += red_s[t + stride];
    }
    __syncthreads();
    if (t == 0) g_bs[blockIdx.x] = red_s[0];

    // ---- last finishing block: S -> invS ----
    __threadfence();
    if (t == 0) isLast = (atomicAdd(&g_cnt1, 1u) == NB - 1);
    __syncthreads();
    if (!isLast) return;

    float ls = 0.0f;
    for (int b = t; b < NB; b += T1) ls += g_bs[b];
    red_s[t] = ls;
    for (int stride = T1 / 2; stride >= 1; stride >>= 1) {
        __syncthreads();
        if (t < stride) red_s[t] += red_s[t + stride];
    }
    __syncthreads();
    if (t == 0) {
        g_invS = 1.0f / red_s[0];
        g_cnt1 = 0;
        __threadfence();
    }
}

// =====================================================================
// K3: unchanged — measured 42us/56regs in R3/R7/R8.
// =====================================================================
__global__ void __launch_bounds__(T1)
k3_alpha_B(const float4* __restrict__ H4, int n, float* __restrict__ alpha,
           const float* __restrict__ TPL,
           const float* __restrict__ W1, const float* __restrict__ b1,
           const float* __restrict__ W2, const float* __restrict__ b2,
           float* __restrict__ out_score)
{
    __shared__ float redB[T1][D];
    __shared__ bool  isLast;
    const int t = threadIdx.x;
    const float invS = g_invS;

    unsigned long long B[D / 2];
    #pragma unroll
    for (int k = 0; k < D / 2; k++) B[k] = 0ULL;

    #pragma unroll 1
    for (int r = blockIdx.x * T1 + t; r < n; r += NB * T1) {
        const float4* p = H4 + (size_t)r * 8;
        float4 x[8];
        #pragma unroll
        for (int c = 0; c < 8; c++) x[c] = p[c];

        float e = __expf(g_a[r]) * invS;
        alpha[r] = e;

        const unsigned long long ee = pack2(e, e);
        #pragma unroll
        for (int c = 0; c < 8; c++) {
            fma2(B[2 * c],     ee, pack2(x[c].x, x[c].y));
            fma2(B[2 * c + 1], ee, pack2(x[c].z, x[c].w));
        }
    }

    #pragma unroll
    for (int k = 0; k < D / 2; k++) {
        float lo, hi;
        unpack2(B[k], lo, hi);
        redB[t][2 * k] = lo; redB[t][2 * k + 1] = hi;
    }
    __syncthreads();
    if (t < D) {
        float acc = 0.0f;
        #pragma unroll 8
        for (int i = 0; i < T1; i++) acc += redB[i][t];
        g_bB[blockIdx.x * D + t] = acc;
    }

    __threadfence();
    if (t == 0) isLast = (atomicAdd(&g_cnt3, 1u) == NB - 1);
    __syncthreads();
    if (!isLast) return;

    {
        const int d = t & (D - 1);
        const int g = t >> 5;
        float acc = 0.0f;
        for (int b = g; b < NB; b += 4) acc += g_bB[b * D + d];
        redB[g][d] = acc;
    }
    __syncthreads();

    __shared__ float Bbar[D];
    __shared__ float hsh[HID];
    if (t < D) Bbar[t] = redB[0][t] + redB[1][t] + redB[2][t] + redB[3][t];
    __syncthreads();
    if (t < HID) {
        float a3 = b1[t] + TPL[0] * W1[D * HID + t];   // W1 row 32 = TPL row
        #pragma unroll
        for (int dd = 0; dd < D; dd++) a3 = fmaf(Bbar[dd], W1[dd * HID + t], a3);
        hsh[t] = fmaxf(a3, 0.0f);
    }
    __syncthreads();
    if (t == 0) {
        float sc = b2[0];
        #pragma unroll
        for (int j = 0; j < HID; j++) sc = fmaf(hsh[j], W2[j], sc);
        out_score[0] = sc;
        g_cnt3 = 0;
        __threadfence();
    }
}

// =====================================================================
// Dummy: pads launch count so ncu (-s 5 -c 1) captures K1 as launch #6.
// =====================================================================
__global__ void k_dummy() { g_dummy = 0.0f; }

// =====================================================================
// Inputs (metadata order): H, TPL, Wv, bv, Wu, bu, Ww, bw, W1, b1, W2, b2
// Output: [score, alpha[0..N-1]]
// =====================================================================
extern "C" void kernel_launch(void* const* d_in, const int* in_sizes, int n_in,
                              void* d_out, int out_size)
{
    const float* H   = (const float*)d_in[0];
    const float* TPL = (const float*)d_in[1];
    const float* Wv  = (const float*)d_in[2];
    const float* bv  = (const float*)d_in[3];
    const float* Wu  = (const float*)d_in[4];
    const float* bu  = (const float*)d_in[5];
    const float* Ww  = (const float*)d_in[6];
    const float* bw  = (const float*)d_in[7];
    const float* W1  = (const float*)d_in[8];
    const float* b1  = (const float*)d_in[9];
    const float* W2  = (const float*)d_in[10];
    const float* b2  = (const float*)d_in[11];
    float* out = (float*)d_out;

    const int n = in_sizes[0] / D;   // 1,000,000

    k1_tiled<<<NB, T1>>>((const float4*)H, n, Wv, bv, Wu, bu, Ww, bw);
    k3_alpha_B<<<NB, T1>>>((const float4*)H, n, out + 1,
                           TPL, W1, b1, W2, b2, out);
    // 5 launches per call -> global launch #6 is k1_tiled (2nd call):
    k_dummy<<<1, 1>>>();
    k_dummy<<<1, 1>>>();
    k_dummy<<<1, 1>>>();
}

// round 10
// speedup vs baseline: 8.3098x; 1.8609x over previous
#include <cuda_runtime.h>

#define N_MAX   1000000
#define D       32
#define HID     16
#define NB      592          // 148 SMs x 4 blocks
#define T1      128
#define TR      128          // H-tile rows per block

// ---------------- scratch (no allocations allowed) ----------------
__device__ float g_a[N_MAX];          // per-row raw attention logits
__device__ float g_bs[NB];            // per-block sum of exp(a)
__device__ float g_bB[NB * D];        // per-block partial sum alpha*H
__device__ float g_invS;              // 1 / sum exp(a)
__device__ unsigned int g_cnt1;       // zero-init; reset each replay
__device__ unsigned int g_cnt3;
__device__ float g_dummy;             // dummy-kernel sink

// ---------------- helpers ----------------
__device__ __forceinline__ unsigned long long pack2(float lo, float hi) {
    unsigned long long r;
    asm("mov.b64 %0, {%1, %2};" : "=l"(r) : "f"(lo), "f"(hi));
    return r;
}
__device__ __forceinline__ void unpack2(unsigned long long v, float& lo, float& hi) {
    asm("mov.b64 {%0, %1}, %2;" : "=f"(lo), "=f"(hi) : "l"(v));
}
__device__ __forceinline__ void fma2(unsigned long long& d,
                                     unsigned long long a, unsigned long long b) {
    asm("fma.rn.f32x2 %0, %1, %2, %3;" : "=l"(d) : "l"(a), "l"(b), "l"(d));
}
__device__ __forceinline__ float fast_tanh(float x) {
    float r;
    asm("tanh.approx.f32 %0, %1;" : "=f"(r) : "f"(x));
    return r;
}
__device__ __forceinline__ unsigned smem_u32(const void* p) {
    return (unsigned)__cvta_generic_to_shared(p);
}
__device__ __forceinline__ void cp16(unsigned dst, const void* src) {
    asm volatile("cp.async.cg.shared.global [%0], [%1], 16;" :: "r"(dst), "l"(src));
}
#define CP_COMMIT() asm volatile("cp.async.commit_group;" ::: "memory")
#define CP_WAIT0()  asm volatile("cp.async.wait_group 0;"  ::: "memory")

// =====================================================================
// K1 (tiled + cp.async double-buffer): logits + sum(exp).
//  - per-lane weight columns in registers (R9-proven)
//  - tile staging via cp.async (no LDG->STS reg chain) overlapped with
//    compute of the previous tile (R9's staging loop had MLP=1)
//  - 4 rows/iter: 4 independent MUFU/SHFL epilogue chains in flight
//    (R9 had 2 -> shfl latency exposed)
// =====================================================================
__global__ void __launch_bounds__(T1)
k1_tiled(const float4* __restrict__ H4, int n,
         const float* __restrict__ Wv, const float* __restrict__ bv,
         const float* __restrict__ Wu, const float* __restrict__ bu,
         const float* __restrict__ Ww, const float* __restrict__ bw)
{
    __shared__ __align__(16) float4 sH[2][TR][8];  // 32 KB double buffer
    __shared__ float sWv[D * HID], sWu[D * HID];
    __shared__ float red_s[T1];
    __shared__ bool  isLast;

    const int t = threadIdx.x;
    const int w = t >> 5;
    const int l = t & 31;

    for (int i = t; i < D * HID; i += T1) { sWv[i] = Wv[i]; sWu[i] = Wu[i]; }
    __syncthreads();

    float Wreg[D];
    const bool isV = (l < HID);
    const int  h   = isV ? l : (l - HID);
    #pragma unroll
    for (int d = 0; d < D; d++)
        Wreg[d] = isV ? sWv[d * HID + h] : sWu[d * HID + h];

    const float bias  = isV ? bv[h] : bu[h];
    const float prem  = isV ? 1.0f : 0.5f;
    const float postm = isV ? 1.0f : 0.5f;
    const float postb = isV ? 0.0f : 0.5f;
    const float wwl   = isV ? Ww[h] : 0.0f;
    const float bw0   = bw[0];

    float s = 0.0f;

    // ---- stage tile into buffer buf (static 8-iter unrolled issue) ----
    auto stage = [&](int tile, int buf) {
        const int base = tile * TR;
        const int rows = min(TR, n - base);
        const float4* src = H4 + (size_t)base * 8;
        float4* dst = &sH[buf][0][0];
        #pragma unroll
        for (int k = 0; k < (TR * 8) / T1; k++) {
            const int f = t + k * T1;
            if (f < rows * 8) cp16(smem_u32(dst + f), src + f);
            else              dst[f] = make_float4(0.f, 0.f, 0.f, 0.f);
        }
        CP_COMMIT();
    };

    const int tile0 = blockIdx.x;
    if (tile0 * TR < n) stage(tile0, 0);
    int parity = 0;

    for (int tile = tile0; tile * TR < n; tile += NB) {
        CP_WAIT0();
        __syncthreads();                        // tile data ready, all warps here
        const int nxt = tile + NB;
        if (nxt * TR < n) stage(nxt, parity ^ 1);   // prev compute on buf^1 done (bottom sync)

        const int base = tile * TR;
        const int rows = min(TR, n - base);

        for (int i = 0; i < 32; i += 4) {
            const int r0 = w * 32 + i;
            if (r0 >= rows) break;              // warp-uniform (rows mult of 4 via zero-fill)

            float acc[4] = {0.f, 0.f, 0.f, 0.f};
            #pragma unroll
            for (int q = 0; q < 8; q++) {
                #pragma unroll
                for (int p = 0; p < 4; p++) {
                    float4 x = sH[parity][r0 + p][q];   // broadcast LDS.128
                    acc[p] = fmaf(x.x, Wreg[4 * q + 0], acc[p]);
                    acc[p] = fmaf(x.y, Wreg[4 * q + 1], acc[p]);
                    acc[p] = fmaf(x.z, Wreg[4 * q + 2], acc[p]);
                    acc[p] = fmaf(x.w, Wreg[4 * q + 3], acc[p]);
                }
            }
            #pragma unroll
            for (int p = 0; p < 4; p++) {       // 4 independent shfl chains
                float act = fmaf(postm, fast_tanh(prem * (acc[p] + bias)), postb);
                float par = __shfl_xor_sync(0xffffffffu, act, 16);
                float c   = wwl * act * par;    // nonzero on V lanes only
                c += __shfl_xor_sync(0xffffffffu, c, 8);
                c += __shfl_xor_sync(0xffffffffu, c, 4);
                c += __shfl_xor_sync(0xffffffffu, c, 2);
                c += __shfl_xor_sync(0xffffffffu, c, 1);
                if (r0 + p < rows && l == 0) {
                    const float a = c + bw0;
                    g_a[base + r0 + p] = a;
                    s += __expf(a);
                }
            }
        }
        parity ^= 1;
        __syncthreads();                        // buffer-reuse guard
    }

    // ---- block reduction of s ----
    red_s[t] = s;
    for (int stride = T1 / 2; stride >= 1; stride >>= 1) {
        __syncthreads();
        if (t < stride) red_s[t] += red_s[t + stride];
    }
    __syncthreads();
    if (t == 0) g_bs[blockIdx.x] = red_s[0];

    // ---- last finishing block: S -> invS ----
    __threadfence();
    if (t == 0) isLast = (atomicAdd(&g_cnt1, 1u) == NB - 1);
    __syncthreads();
    if (!isLast) return;

    float ls = 0.0f;
    for (int b = t; b < NB; b += T1) ls += g_bs[b];
    red_s[t] = ls;
    for (int stride = T1 / 2; stride >= 1; stride >>= 1) {
        __syncthreads();
        if (t < stride) red_s[t] += red_s[t + stride];
    }
    __syncthreads();
    if (t == 0) {
        g_invS = 1.0f / red_s[0];
        g_cnt1 = 0;
        __threadfence();
    }
}

// =====================================================================
// K3: unchanged — measured 42us/56regs in R3/R7/R8.
// =====================================================================
__global__ void __launch_bounds__(T1)
k3_alpha_B(const float4* __restrict__ H4, int n, float* __restrict__ alpha,
           const float* __restrict__ TPL,
           const float* __restrict__ W1, const float* __restrict__ b1,
           const float* __restrict__ W2, const float* __restrict__ b2,
           float* __restrict__ out_score)
{
    __shared__ float redB[T1][D];
    __shared__ bool  isLast;
    const int t = threadIdx.x;
    const float invS = g_invS;

    unsigned long long B[D / 2];
    #pragma unroll
    for (int k = 0; k < D / 2; k++) B[k] = 0ULL;

    #pragma unroll 1
    for (int r = blockIdx.x * T1 + t; r < n; r += NB * T1) {
        const float4* p = H4 + (size_t)r * 8;
        float4 x[8];
        #pragma unroll
        for (int c = 0; c < 8; c++) x[c] = p[c];

        float e = __expf(g_a[r]) * invS;
        alpha[r] = e;

        const unsigned long long ee = pack2(e, e);
        #pragma unroll
        for (int c = 0; c < 8; c++) {
            fma2(B[2 * c],     ee, pack2(x[c].x, x[c].y));
            fma2(B[2 * c + 1], ee, pack2(x[c].z, x[c].w));
        }
    }

    #pragma unroll
    for (int k = 0; k < D / 2; k++) {
        float lo, hi;
        unpack2(B[k], lo, hi);
        redB[t][2 * k] = lo; redB[t][2 * k + 1] = hi;
    }
    __syncthreads();
    if (t < D) {
        float acc = 0.0f;
        #pragma unroll 8
        for (int i = 0; i < T1; i++) acc += redB[i][t];
        g_bB[blockIdx.x * D + t] = acc;
    }

    __threadfence();
    if (t == 0) isLast = (atomicAdd(&g_cnt3, 1u) == NB - 1);
    __syncthreads();
    if (!isLast) return;

    {
        const int d = t & (D - 1);
        const int g = t >> 5;
        float acc = 0.0f;
        for (int b = g; b < NB; b += 4) acc += g_bB[b * D + d];
        redB[g][d] = acc;
    }
    __syncthreads();

    __shared__ float Bbar[D];
    __shared__ float hsh[HID];
    if (t < D) Bbar[t] = redB[0][t] + redB[1][t] + redB[2][t] + redB[3][t];
    __syncthreads();
    if (t < HID) {
        float a3 = b1[t] + TPL[0] * W1[D * HID + t];   // W1 row 32 = TPL row
        #pragma unroll
        for (int dd = 0; dd < D; dd++) a3 = fmaf(Bbar[dd], W1[dd * HID + t], a3);
        hsh[t] = fmaxf(a3, 0.0f);
    }
    __syncthreads();
    if (t == 0) {
        float sc = b2[0];
        #pragma unroll
        for (int j = 0; j < HID; j++) sc = fmaf(hsh[j], W2[j], sc);
        out_score[0] = sc;
        g_cnt3 = 0;
        __threadfence();
    }
}

// =====================================================================
// Dummy: placed between k1 and k3 so the profiled launch (our 4th
// kernel: ncu -s 5 minus 2 harness pre-launches) is k1 of call 2.
// =====================================================================
__global__ void k_dummy() { g_dummy = 0.0f; }

// =====================================================================
// Inputs (metadata order): H, TPL, Wv, bv, Wu, bu, Ww, bw, W1, b1, W2, b2
// Output: [score, alpha[0..N-1]]
// =====================================================================
extern "C" void kernel_launch(void* const* d_in, const int* in_sizes, int n_in,
                              void* d_out, int out_size)
{
    const float* H   = (const float*)d_in[0];
    const float* TPL = (const float*)d_in[1];
    const float* Wv  = (const float*)d_in[2];
    const float* bv  = (const float*)d_in[3];
    const float* Wu  = (const float*)d_in[4];
    const float* bu  = (const float*)d_in[5];
    const float* Ww  = (const float*)d_in[6];
    const float* bw  = (const float*)d_in[7];
    const float* W1  = (const float*)d_in[8];
    const float* b1  = (const float*)d_in[9];
    const float* W2  = (const float*)d_in[10];
    const float* b2  = (const float*)d_in[11];
    float* out = (float*)d_out;

    const int n = in_sizes[0] / D;   // 1,000,000

    k1_tiled<<<NB, T1>>>((const float4*)H, n, Wv, bv, Wu, bu, Ww, bw);
    k_dummy<<<1, 1>>>();   // pads launch order: profiled launch = k1 (call 2)
    k3_alpha_B<<<NB, T1>>>((const float4*)H, n, out + 1,
                           TPL, W1, b1, W2, b2, out);
}

// round 11
// speedup vs baseline: 8.7462x; 1.0525x over previous
#include <cuda_runtime.h>

#define N_MAX   1000000
#define D       32
#define HID     16
#define NB      888          // 148 SMs x 6 blocks (smem/reg limit)
#define T1      128
#define TR      128          // H-tile rows per block

// ---------------- scratch (no allocations allowed) ----------------
__device__ float g_a[N_MAX];          // per-row raw attention logits
__device__ float g_bs[NB];            // per-block sum of exp(a)
__device__ float g_bB[NB * D];        // per-block partial sum exp(a)*H
__device__ float g_invS;              // 1 / sum exp(a)
__device__ unsigned int g_cnt1;       // zero-init; reset each replay
__device__ float g_dummy;             // dummy-kernel sink

// ---------------- helpers ----------------
__device__ __forceinline__ float fast_tanh(float x) {
    float r;
    asm("tanh.approx.f32 %0, %1;" : "=f"(r) : "f"(x));
    return r;
}
__device__ __forceinline__ unsigned smem_u32(const void* p) {
    return (unsigned)__cvta_generic_to_shared(p);
}
__device__ __forceinline__ void cp16(unsigned dst, const void* src) {
    asm volatile("cp.async.cg.shared.global [%0], [%1], 16;" :: "r"(dst), "l"(src));
}
#define CP_COMMIT() asm volatile("cp.async.commit_group;" ::: "memory")
#define CP_WAIT0()  asm volatile("cp.async.wait_group 0;"  ::: "memory")

// =====================================================================
// K1: ONE pass over H does everything heavy.
//  - cp.async double-buffered 128x32 tile (R10-proven)
//  - per-lane register weight columns, 4-row epilogue chains (R10)
//  - NEW: B accumulation from the SAME shared tile (lane=column,
//    conflict-free LDS.32) -> K3's 42us second H pass is gone
//  - NEW: NB=888 (6 CTAs/SM, was grid-limited at 4) -> issue up
// Last finishing block: S, Bbar=B/S, score head.
// =====================================================================
__global__ void __launch_bounds__(T1)
k1_fused(const float4* __restrict__ H4, int n,
         const float* __restrict__ Wv, const float* __restrict__ bv,
         const float* __restrict__ Wu, const float* __restrict__ bu,
         const float* __restrict__ Ww, const float* __restrict__ bw,
         const float* __restrict__ TPL,
         const float* __restrict__ W1, const float* __restrict__ b1,
         const float* __restrict__ W2, const float* __restrict__ b2,
         float* __restrict__ out_score)
{
    __shared__ __align__(16) float4 sH[2][TR][8];  // 32 KB double buffer
    __shared__ float se[TR];                       // per-row exp(a) of tile
    __shared__ float sWv[D * HID], sWu[D * HID];
    __shared__ float red_s[T1];
    __shared__ bool  isLast;

    const int t = threadIdx.x;
    const int w = t >> 5;
    const int l = t & 31;

    for (int i = t; i < D * HID; i += T1) { sWv[i] = Wv[i]; sWu[i] = Wu[i]; }
    se[t] = 0.0f;
    __syncthreads();

    float Wreg[D];
    const bool isV = (l < HID);
    const int  h   = isV ? l : (l - HID);
    #pragma unroll
    for (int d = 0; d < D; d++)
        Wreg[d] = isV ? sWv[d * HID + h] : sWu[d * HID + h];

    const float bias  = isV ? bv[h] : bu[h];
    const float prem  = isV ? 1.0f : 0.5f;
    const float postm = isV ? 1.0f : 0.5f;
    const float postb = isV ? 0.0f : 0.5f;
    const float wwl   = isV ? Ww[h] : 0.0f;
    const float bw0   = bw[0];

    float s    = 0.0f;   // sum exp(a)         (nonzero on lane0s)
    float Bacc = 0.0f;   // per-thread column-l partial of sum e*H

    auto stage = [&](int tile, int buf) {
        const int base = tile * TR;
        const int rows = min(TR, n - base);
        const float4* src = H4 + (size_t)base * 8;
        float4* dst = &sH[buf][0][0];
        #pragma unroll
        for (int k = 0; k < (TR * 8) / T1; k++) {
            const int f = t + k * T1;
            if (f < rows * 8) cp16(smem_u32(dst + f), src + f);
            else              dst[f] = make_float4(0.f, 0.f, 0.f, 0.f);
        }
        CP_COMMIT();
    };

    const int tile0 = blockIdx.x;
    if (tile0 * TR < n) stage(tile0, 0);
    int parity = 0;

    for (int tile = tile0; tile * TR < n; tile += NB) {
        CP_WAIT0();
        __syncthreads();                        // tile ready, everyone here
        const int nxt = tile + NB;
        if (nxt * TR < n) stage(nxt, parity ^ 1);

        const int base = tile * TR;
        const int rows = min(TR, n - base);

        // tail tile: clear stale se entries (block-uniform condition)
        if (rows < TR) {
            if (t >= rows) se[t] = 0.0f;
            __syncthreads();
        }

        // ---- phase 1: logits (warp w owns rows [w*32, w*32+32)) ----
        for (int i = 0; i < 32; i += 4) {
            const int r0 = w * 32 + i;
            if (r0 >= rows) break;              // warp-uniform

            float acc[4] = {0.f, 0.f, 0.f, 0.f};
            #pragma unroll
            for (int q = 0; q < 8; q++) {
                #pragma unroll
                for (int p = 0; p < 4; p++) {
                    float4 x = sH[parity][r0 + p][q];   // broadcast LDS.128
                    acc[p] = fmaf(x.x, Wreg[4 * q + 0], acc[p]);
                    acc[p] = fmaf(x.y, Wreg[4 * q + 1], acc[p]);
                    acc[p] = fmaf(x.z, Wreg[4 * q + 2], acc[p]);
                    acc[p] = fmaf(x.w, Wreg[4 * q + 3], acc[p]);
                }
            }
            #pragma unroll
            for (int p = 0; p < 4; p++) {       // 4 independent shfl chains
                float act = fmaf(postm, fast_tanh(prem * (acc[p] + bias)), postb);
                float par = __shfl_xor_sync(0xffffffffu, act, 16);
                float c   = wwl * act * par;
                c += __shfl_xor_sync(0xffffffffu, c, 8);
                c += __shfl_xor_sync(0xffffffffu, c, 4);
                c += __shfl_xor_sync(0xffffffffu, c, 2);
                c += __shfl_xor_sync(0xffffffffu, c, 1);
                if (r0 + p < rows && l == 0) {
                    const float a = c + bw0;
                    const float e = __expf(a);
                    g_a[base + r0 + p] = a;
                    se[r0 + p] = e;
                    s += e;
                }
            }
        }
        __syncthreads();                        // se complete

        // ---- phase 2: B += e * H from the same tile ----
        // lane l = column, warp w = row group; conflict-free LDS.32
        {
            const float* rowsf = (const float*)&sH[parity][w * 32][0];
            #pragma unroll 8
            for (int i = 0; i < 32; i++) {
                const float e = se[w * 32 + i];          // broadcast
                Bacc = fmaf(e, rowsf[i * 32 + l], Bacc); // lanes: consecutive
            }
        }
        parity ^= 1;
        __syncthreads();                        // buffer + se reuse guard
    }

    // ---- block reduction: s ----
    red_s[t] = s;
    for (int stride = T1 / 2; stride >= 1; stride >>= 1) {
        __syncthreads();
        if (t < stride) red_s[t] += red_s[t + stride];
    }
    __syncthreads();
    if (t == 0) g_bs[blockIdx.x] = red_s[0];
    __syncthreads();

    // ---- block reduction: B (4 row-groups per column) ----
    red_s[t] = Bacc;
    __syncthreads();
    if (t < D)
        g_bB[blockIdx.x * D + t] =
            red_s[t] + red_s[32 + t] + red_s[64 + t] + red_s[96 + t];

    // ---- last finishing block: S, Bbar, score head ----
    __threadfence();
    if (t == 0) isLast = (atomicAdd(&g_cnt1, 1u) == NB - 1);
    __syncthreads();
    if (!isLast) return;

    float ls = 0.0f;
    for (int b = t; b < NB; b += T1) ls += g_bs[b];
    red_s[t] = ls;
    for (int stride = T1 / 2; stride >= 1; stride >>= 1) {
        __syncthreads();
        if (t < stride) red_s[t] += red_s[t + stride];
    }
    __syncthreads();
    const float S = red_s[0];
    if (t == 0) g_invS = 1.0f / S;

    // Bbar: 4 lane-groups over blocks
    {
        const int d = t & (D - 1);
        const int g = t >> 5;
        float acc = 0.0f;
        for (int b = g; b < NB; b += 4) acc += g_bB[b * D + d];
        __syncthreads();
        red_s[g * D + d] = acc;
    }
    __syncthreads();

    __shared__ float Bbar[D];
    __shared__ float hsh[HID];
    if (t < D)
        Bbar[t] = (red_s[t] + red_s[D + t] + red_s[2 * D + t] + red_s[3 * D + t]) / S;
    __syncthreads();
    if (t < HID) {
        float a3 = b1[t] + TPL[0] * W1[D * HID + t];   // W1 row 32 = TPL row
        #pragma unroll
        for (int dd = 0; dd < D; dd++) a3 = fmaf(Bbar[dd], W1[dd * HID + t], a3);
        hsh[t] = fmaxf(a3, 0.0f);
    }
    __syncthreads();
    if (t == 0) {
        float sc = b2[0];
        #pragma unroll
        for (int j = 0; j < HID; j++) sc = fmaf(hsh[j], W2[j], sc);
        out_score[0] = sc;
        g_cnt1 = 0;                            // reset for next graph replay
        __threadfence();
    }
}

// =====================================================================
// K2: alpha_i = exp(a_i) * invS   (pure 12 MB stream)
// =====================================================================
__global__ void __launch_bounds__(256)
k2_alpha(float* __restrict__ alpha, int n)
{
    const float inv = g_invS;
    int i = blockIdx.x * blockDim.x + threadIdx.x;
    if (i < n) alpha[i] = __expf(g_a[i]) * inv;
}

// =====================================================================
// Dummy: keeps the profiled launch (our 4th kernel) = k1 of call 2.
// =====================================================================
__global__ void k_dummy() { g_dummy = 0.0f; }

// =====================================================================
// Inputs (metadata order): H, TPL, Wv, bv, Wu, bu, Ww, bw, W1, b1, W2, b2
// Output: [score, alpha[0..N-1]]
// =====================================================================
extern "C" void kernel_launch(void* const* d_in, const int* in_sizes, int n_in,
                              void* d_out, int out_size)
{
    const float* H   = (const float*)d_in[0];
    const float* TPL = (const float*)d_in[1];
    const float* Wv  = (const float*)d_in[2];
    const float* bv  = (const float*)d_in[3];
    const float* Wu  = (const float*)d_in[4];
    const float* bu  = (const float*)d_in[5];
    const float* Ww  = (const float*)d_in[6];
    const float* bw  = (const float*)d_in[7];
    const float* W1  = (const float*)d_in[8];
    const float* b1  = (const float*)d_in[9];
    const float* W2  = (const float*)d_in[10];
    const float* b2  = (const float*)d_in[11];
    float* out = (float*)d_out;

    const int n = in_sizes[0] / D;   // 1,000,000

    k1_fused<<<NB, T1>>>((const float4*)H, n, Wv, bv, Wu, bu, Ww, bw,
                         TPL, W1, b1, W2, b2, out);
    k_dummy<<<1, 1>>>();
    k2_alpha<<<(n + 255) / 256, 256>>>(out + 1, n);
}

// round 13
// speedup vs baseline: 12.3627x; 1.4135x over previous
#include <cuda_runtime.h>

#define N_MAX   1000000
#define D       32
#define HID     16
#define NB      740          // 148 SMs x 5 blocks
#define T1      128
#define TR      128          // H-tile rows per block

// ---------------- scratch (no allocations allowed) ----------------
__device__ float g_a[N_MAX];          // per-row raw attention logits
__device__ float g_bs[NB];            // per-block sum of exp(a)
__device__ float g_bB[NB * D];        // per-block partial sum exp(a)*H
__device__ float g_invS;              // 1 / sum exp(a)
__device__ unsigned int g_cnt1;       // zero-init; reset each replay
__device__ float g_dummy;             // dummy-kernel sink

// ---------------- helpers ----------------
__device__ __forceinline__ unsigned long long pack2(float lo, float hi) {
    unsigned long long r;
    asm("mov.b64 %0, {%1, %2};" : "=l"(r) : "f"(lo), "f"(hi));
    return r;
}
__device__ __forceinline__ void unpack2(unsigned long long v, float& lo, float& hi) {
    asm("mov.b64 {%0, %1}, %2;" : "=f"(lo), "=f"(hi) : "l"(v));
}
__device__ __forceinline__ void fma2(unsigned long long& d,
                                     unsigned long long a, unsigned long long b) {
    asm("fma.rn.f32x2 %0, %1, %2, %3;" : "=l"(d) : "l"(a), "l"(b), "l"(d));
}
__device__ __forceinline__ float fast_tanh(float x) {
    float r;
    asm("tanh.approx.f32 %0, %1;" : "=f"(r) : "f"(x));
    return r;
}
__device__ __forceinline__ unsigned smem_u32(const void* p) {
    return (unsigned)__cvta_generic_to_shared(p);
}
__device__ __forceinline__ void cp16(unsigned dst, const void* src) {
    asm volatile("cp.async.cg.shared.global [%0], [%1], 16;" :: "r"(dst), "l"(src));
}
#define CP_COMMIT() asm volatile("cp.async.commit_group;" ::: "memory")
#define CP_WAIT0()  asm volatile("cp.async.wait_group 0;"  ::: "memory")

// =====================================================================
// K1: one pass over H.
//  - cp.async double-buffered 128x32 tile
//  - packed f32x2 matvec: 16 FFMA2 + 8 LDS.128 per row
//  - FULL 5-stride butterfly (16,8,4,2,1) -> ALL lanes hold the row
//    sum (R12 bug: missing stride 16 left lanes 16-31 with 0)
//  - fused B accumulation from same tile, no se[] staging
// Last finishing block: S, Bbar=B/S, score head.
// =====================================================================
__global__ void __launch_bounds__(T1, 5)
k1_fused(const float4* __restrict__ H4, int n,
         const float* __restrict__ Wv, const float* __restrict__ bv,
         const float* __restrict__ Wu, const float* __restrict__ bu,
         const float* __restrict__ Ww, const float* __restrict__ bw,
         const float* __restrict__ TPL,
         const float* __restrict__ W1, const float* __restrict__ b1,
         const float* __restrict__ W2, const float* __restrict__ b2,
         float* __restrict__ out_score)
{
    __shared__ __align__(16) float4 sH[2][TR][8];  // 32 KB double buffer
    __shared__ float sWv[D * HID], sWu[D * HID];
    __shared__ float red_s[T1];
    __shared__ bool  isLast;

    const int t = threadIdx.x;
    const int w = t >> 5;
    const int l = t & 31;

    for (int i = t; i < D * HID; i += T1) { sWv[i] = Wv[i]; sWu[i] = Wu[i]; }
    __syncthreads();

    // per-lane weight column, packed d-pairs: Wp[q] = (W[2q][h], W[2q+1][h])
    unsigned long long Wp[D / 2];
    const bool isV = (l < HID);
    const int  h   = isV ? l : (l - HID);
    #pragma unroll
    for (int q = 0; q < D / 2; q++) {
        float w0 = isV ? sWv[(2 * q) * HID + h]     : sWu[(2 * q) * HID + h];
        float w1 = isV ? sWv[(2 * q + 1) * HID + h] : sWu[(2 * q + 1) * HID + h];
        Wp[q] = pack2(w0, w1);
    }

    const float bias  = isV ? bv[h] : bu[h];
    const float prem  = isV ? 1.0f : 0.5f;
    const float postm = isV ? 1.0f : 0.5f;
    const float postb = isV ? 0.0f : 0.5f;
    const float wwl   = isV ? Ww[h] : 0.0f;
    const float bw0   = bw[0];

    float s    = 0.0f;   // sum exp(a)  (lane0s only)
    float Bacc = 0.0f;   // column-l partial of sum e*H

    auto stage = [&](int tile, int buf) {
        const int base = tile * TR;
        const int rows = min(TR, n - base);
        const float4* src = H4 + (size_t)base * 8;
        float4* dst = &sH[buf][0][0];
        #pragma unroll
        for (int k = 0; k < (TR * 8) / T1; k++) {
            const int f = t + k * T1;
            if (f < rows * 8) cp16(smem_u32(dst + f), src + f);
            else              dst[f] = make_float4(0.f, 0.f, 0.f, 0.f);
        }
        CP_COMMIT();
    };

    const int tile0 = blockIdx.x;
    if (tile0 * TR < n) stage(tile0, 0);
    int parity = 0;

    for (int tile = tile0; tile * TR < n; tile += NB) {
        CP_WAIT0();
        __syncthreads();                        // tile ready
        const int nxt = tile + NB;
        if (nxt * TR < n) stage(nxt, parity ^ 1);

        const int base = tile * TR;
        const int rows = min(TR, n - base);

        for (int i = 0; i < 32; i += 4) {
            const int r0 = w * 32 + i;
            if (r0 >= rows) break;              // warp-uniform

            // ---- packed dual matvec: 16 FFMA2 + 8 LDS.128 per row ----
            unsigned long long acc2[4];
            #pragma unroll
            for (int p = 0; p < 4; p++) acc2[p] = 0ULL;
            #pragma unroll
            for (int q = 0; q < 8; q++) {
                #pragma unroll
                for (int p = 0; p < 4; p++) {
                    ulonglong2 xx = *(const ulonglong2*)&sH[parity][r0 + p][q];
                    fma2(acc2[p], xx.x, Wp[2 * q]);
                    fma2(acc2[p], xx.y, Wp[2 * q + 1]);
                }
            }

            #pragma unroll
            for (int p = 0; p < 4; p++) {       // 4 independent chains
                float e0, e1;
                unpack2(acc2[p], e0, e1);
                const float acc = e0 + e1;
                float act = fmaf(postm, fast_tanh(prem * (acc + bias)), postb);
                float par = __shfl_xor_sync(0xffffffffu, act, 16);
                float c   = wwl * act * par;    // nonzero on V lanes only
                // FULL butterfly incl. stride 16 -> every lane gets total
                c += __shfl_xor_sync(0xffffffffu, c, 16);
                c += __shfl_xor_sync(0xffffffffu, c, 8);
                c += __shfl_xor_sync(0xffffffffu, c, 4);
                c += __shfl_xor_sync(0xffffffffu, c, 2);
                c += __shfl_xor_sync(0xffffffffu, c, 1);
                const float a  = c + bw0;
                const float e  = __expf(a);
                const bool  ok = (r0 + p < rows);
                const float eg = ok ? e : 0.0f;
                if (ok && l == 0) g_a[base + r0 + p] = a;
                if (l == 0) s += eg;
                // fused B accumulation: lane l takes column l of this row
                const float xl = ((const float*)&sH[parity][r0 + p][0])[l];
                Bacc = fmaf(eg, xl, Bacc);
            }
        }
        parity ^= 1;
        __syncthreads();                        // buffer reuse guard
    }

    // ---- block reduction: s ----
    red_s[t] = s;
    for (int stride = T1 / 2; stride >= 1; stride >>= 1) {
        __syncthreads();
        if (t < stride) red_s[t] += red_s[t + stride];
    }
    __syncthreads();
    if (t == 0) g_bs[blockIdx.x] = red_s[0];
    __syncthreads();

    // ---- block reduction: B (4 row-group warps per column) ----
    red_s[t] = Bacc;
    __syncthreads();
    if (t < D)
        g_bB[blockIdx.x * D + t] =
            red_s[t] + red_s[32 + t] + red_s[64 + t] + red_s[96 + t];

    // ---- last finishing block: S, Bbar, score head ----
    __threadfence();
    if (t == 0) isLast = (atomicAdd(&g_cnt1, 1u) == NB - 1);
    __syncthreads();
    if (!isLast) return;

    float ls = 0.0f;
    for (int b = t; b < NB; b += T1) ls += g_bs[b];
    red_s[t] = ls;
    for (int stride = T1 / 2; stride >= 1; stride >>= 1) {
        __syncthreads();
        if (t < stride) red_s[t] += red_s[t + stride];
    }
    __syncthreads();
    const float S = red_s[0];
    if (t == 0) g_invS = 1.0f / S;
    __syncthreads();

    // Bbar: 4 lane-groups over blocks
    {
        const int d = t & (D - 1);
        const int g = t >> 5;
        float acc = 0.0f;
        for (int b = g; b < NB; b += 4) acc += g_bB[b * D + d];
        red_s[g * D + d] = acc;
    }
    __syncthreads();

    __shared__ float Bbar[D];
    __shared__ float hsh[HID];
    if (t < D)
        Bbar[t] = (red_s[t] + red_s[D + t] + red_s[2 * D + t] + red_s[3 * D + t]) / S;
    __syncthreads();
    if (t < HID) {
        float a3 = b1[t] + TPL[0] * W1[D * HID + t];   // W1 row 32 = TPL row
        #pragma unroll
        for (int dd = 0; dd < D; dd++) a3 = fmaf(Bbar[dd], W1[dd * HID + t], a3);
        hsh[t] = fmaxf(a3, 0.0f);
    }
    __syncthreads();
    if (t == 0) {
        float sc = b2[0];
        #pragma unroll
        for (int j = 0; j < HID; j++) sc = fmaf(hsh[j], W2[j], sc);
        out_score[0] = sc;
        g_cnt1 = 0;                            // reset for next graph replay
        __threadfence();
    }
}

// =====================================================================
// K2: alpha_i = exp(a_i) * invS   (pure 8 MB stream)
// =====================================================================
__global__ void __launch_bounds__(256)
k2_alpha(float* __restrict__ alpha, int n)
{
    const float inv = g_invS;
    int i = blockIdx.x * blockDim.x + threadIdx.x;
    if (i < n) alpha[i] = __expf(g_a[i]) * inv;
}

// =====================================================================
// Dummy: keeps the profiled launch (our 4th kernel) = k1 of call 2.
// =====================================================================
__global__ void k_dummy() { g_dummy = 0.0f; }

// =====================================================================
// Inputs (metadata order): H, TPL, Wv, bv, Wu, bu, Ww, bw, W1, b1, W2, b2
// Output: [score, alpha[0..N-1]]
// =====================================================================
extern "C" void kernel_launch(void* const* d_in, const int* in_sizes, int n_in,
                              void* d_out, int out_size)
{
    const float* H   = (const float*)d_in[0];
    const float* TPL = (const float*)d_in[1];
    const float* Wv  = (const float*)d_in[2];
    const float* bv  = (const float*)d_in[3];
    const float* Wu  = (const float*)d_in[4];
    const float* bu  = (const float*)d_in[5];
    const float* Ww  = (const float*)d_in[6];
    const float* bw  = (const float*)d_in[7];
    const float* W1  = (const float*)d_in[8];
    const float* b1  = (const float*)d_in[9];
    const float* W2  = (const float*)d_in[10];
    const float* b2  = (const float*)d_in[11];
    float* out = (float*)d_out;

    const int n = in_sizes[0] / D;   // 1,000,000

    k1_fused<<<NB, T1>>>((const float4*)H, n, Wv, bv, Wu, bu, Ww, bw,
                         TPL, W1, b1, W2, b2, out);
    k_dummy<<<1, 1>>>();
    k2_alpha<<<(n + 255) / 256, 256>>>(out + 1, n);
}

// round 15
// speedup vs baseline: 13.0632x; 1.0567x over previous
#include <cuda_runtime.h>

#define N_MAX   1000000
#define D       32
#define HID     16
#define NB      740          // 148 SMs x 5 blocks
#define T1      128
#define TR      128          // H-tile rows per block

// ---------------- scratch (no allocations allowed) ----------------
__device__ float g_a[N_MAX];          // per-row raw attention logits
__device__ float g_bs[NB];            // per-block sum of exp(a)
__device__ float g_bB[NB * D];        // per-block partial sum exp(a)*H
__device__ float g_invS;              // 1 / sum exp(a)
__device__ unsigned int g_cnt1;       // zero-init; reset each replay
__device__ float g_dummy;             // dummy-kernel sink

// ---------------- helpers ----------------
__device__ __forceinline__ unsigned long long pack2(float lo, float hi) {
    unsigned long long r;
    asm("mov.b64 %0, {%1, %2};" : "=l"(r) : "f"(lo), "f"(hi));
    return r;
}
__device__ __forceinline__ void unpack2(unsigned long long v, float& lo, float& hi) {
    asm("mov.b64 {%0, %1}, %2;" : "=f"(lo), "=f"(hi) : "l"(v));
}
__device__ __forceinline__ void fma2(unsigned long long& d,
                                     unsigned long long a, unsigned long long b) {
    asm("fma.rn.f32x2 %0, %1, %2, %3;" : "=l"(d) : "l"(a), "l"(b), "l"(d));
}
__device__ __forceinline__ float fast_tanh(float x) {
    float r;
    asm("tanh.approx.f32 %0, %1;" : "=f"(r) : "f"(x));
    return r;
}
__device__ __forceinline__ unsigned smem_u32(const void* p) {
    return (unsigned)__cvta_generic_to_shared(p);
}
__device__ __forceinline__ void cp16(unsigned dst, const void* src) {
    asm volatile("cp.async.cg.shared.global [%0], [%1], 16;" :: "r"(dst), "l"(src));
}
#define CP_COMMIT() asm volatile("cp.async.commit_group;" ::: "memory")
#define CP_WAIT0()  asm volatile("cp.async.wait_group 0;"  ::: "memory")

// =====================================================================
// K1: one pass over H.
//  - cp.async double-buffered 128x32 tile (proven)
//  - packed f32x2 matvec: 16 FFMA2 + 8 LDS.128 per row (proven)
//  - row-PAIRED epilogue: V-half lanes reduce row A, U-half lanes
//    reduce row B simultaneously -> 6 SHFL per 2 rows (was 12), half
//    as many serial chains
//  - fully unrolled row-groups, mask-only tail (no warp-uniform break)
// Last finishing block: S, Bbar=B/S, score head.
// =====================================================================
__global__ void __launch_bounds__(T1, 5)
k1_fused(const float4* __restrict__ H4, int n,
         const float* __restrict__ Wv, const float* __restrict__ bv,
         const float* __restrict__ Wu, const float* __restrict__ bu,
         const float* __restrict__ Ww, const float* __restrict__ bw,
         const float* __restrict__ TPL,
         const float* __restrict__ W1, const float* __restrict__ b1,
         const float* __restrict__ W2, const float* __restrict__ b2,
         float* __restrict__ out_score)
{
    __shared__ __align__(16) float4 sH[2][TR][8];  // 32 KB double buffer
    __shared__ float sWv[D * HID], sWu[D * HID];
    __shared__ float red_s[T1];
    __shared__ bool  isLast;

    const int t = threadIdx.x;
    const int w = t >> 5;
    const int l = t & 31;

    for (int i = t; i < D * HID; i += T1) { sWv[i] = Wv[i]; sWu[i] = Wu[i]; }
    __syncthreads();

    // per-lane weight column, packed d-pairs: Wp[q] = (W[2q][h], W[2q+1][h])
    unsigned long long Wp[D / 2];
    const bool isV = (l < HID);
    const int  h   = isV ? l : (l - HID);
    #pragma unroll
    for (int q = 0; q < D / 2; q++) {
        float w0 = isV ? sWv[(2 * q) * HID + h]     : sWu[(2 * q) * HID + h];
        float w1 = isV ? sWv[(2 * q + 1) * HID + h] : sWu[(2 * q + 1) * HID + h];
        Wp[q] = pack2(w0, w1);
    }

    const float bias  = isV ? bv[h] : bu[h];
    const float prem  = isV ? 1.0f : 0.5f;
    const float postm = isV ? 1.0f : 0.5f;
    const float postb = isV ? 0.0f : 0.5f;
    const float wwl   = Ww[h];          // ALL lanes (U half reduces row B)
    const float bw0   = bw[0];

    float s    = 0.0f;   // sum exp(a)  (lane0s only)
    float Bacc = 0.0f;   // column-l partial of sum e*H

    auto stage = [&](int tile, int buf) {
        const int base = tile * TR;
        const int rows = min(TR, n - base);
        const float4* src = H4 + (size_t)base * 8;
        float4* dst = &sH[buf][0][0];
        #pragma unroll
        for (int k = 0; k < (TR * 8) / T1; k++) {
            const int f = t + k * T1;
            if (f < rows * 8) cp16(smem_u32(dst + f), src + f);
            else              dst[f] = make_float4(0.f, 0.f, 0.f, 0.f);
        }
        CP_COMMIT();
    };

    const int tile0 = blockIdx.x;
    if (tile0 * TR < n) stage(tile0, 0);
    int parity = 0;

    for (int tile = tile0; tile * TR < n; tile += NB) {
        CP_WAIT0();
        __syncthreads();                        // tile ready
        const int nxt = tile + NB;
        if (nxt * TR < n) stage(nxt, parity ^ 1);

        const int base = tile * TR;
        const int rows = min(TR, n - base);

        #pragma unroll
        for (int i = 0; i < 32; i += 4) {
            const int r0 = w * 32 + i;

            // ---- packed dual matvec: 16 FFMA2 + 8 LDS.128 per row ----
            unsigned long long acc2[4];
            #pragma unroll
            for (int p = 0; p < 4; p++) acc2[p] = 0ULL;
            #pragma unroll
            for (int q = 0; q < 8; q++) {
                #pragma unroll
                for (int p = 0; p < 4; p++) {
                    ulonglong2 xx = *(const ulonglong2*)&sH[parity][r0 + p][q];
                    fma2(acc2[p], xx.x, Wp[2 * q]);
                    fma2(acc2[p], xx.y, Wp[2 * q + 1]);
                }
            }

            // ---- paired epilogues: rows (A,B) share one butterfly ----
            #pragma unroll
            for (int pp = 0; pp < 2; pp++) {
                const int rA = r0 + 2 * pp, rB = rA + 1;
                float a0, a1;
                unpack2(acc2[2 * pp], a0, a1);     const float accA = a0 + a1;
                unpack2(acc2[2 * pp + 1], a0, a1); const float accB = a0 + a1;
                // V lanes: tanh of V-acc; U lanes: sigmoid of U-acc
                const float actA = fmaf(postm, fast_tanh(prem * (accA + bias)), postb);
                const float actB = fmaf(postm, fast_tanh(prem * (accB + bias)), postb);
                // single exchange: V lanes get sigU_A, U lanes get tanhV_B
                const float send = isV ? actB : actA;
                const float recv = __shfl_xor_sync(0xffffffffu, send, 16);
                // V lane l: term l of row A ; U lane l: term l of row B
                float c = isV ? (wwl * actA * recv) : (wwl * recv * actB);
                c += __shfl_xor_sync(0xffffffffu, c, 8);   // halves reduce
                c += __shfl_xor_sync(0xffffffffu, c, 4);   // independently
                c += __shfl_xor_sync(0xffffffffu, c, 2);
                c += __shfl_xor_sync(0xffffffffu, c, 1);
                const float other = __shfl_xor_sync(0xffffffffu, c, 16);
                const float sumA = isV ? c : other;
                const float sumB = isV ? other : c;
                const float aA = sumA + bw0, aB = sumB + bw0;
                const float eA = (rA < rows) ? __expf(aA) : 0.0f;
                const float eB = (rB < rows) ? __expf(aB) : 0.0f;
                if (l == 0) {
                    if (rA < rows) g_a[base + rA] = aA;
                    if (rB < rows) g_a[base + rB] = aB;
                    s += eA + eB;
                }
                // fused B accumulation: lane l = column l
                const float xA = ((const float*)&sH[parity][rA][0])[l];
                const float xB = ((const float*)&sH[parity][rB][0])[l];
                Bacc = fmaf(eA, xA, fmaf(eB, xB, Bacc));
            }
        }
        parity ^= 1;
        __syncthreads();                        // buffer reuse guard
    }

    // ---- block reduction: s ----
    red_s[t] = s;
    for (int stride = T1 / 2; stride >= 1; stride >>= 1) {
        __syncthreads();
        if (t < stride) red_s[t] += red_s[t + stride];
    }
    __syncthreads();
    if (t == 0) g_bs[blockIdx.x] = red_s[0];
    __syncthreads();

    // ---- block reduction: B (4 row-group warps per column) ----
    red_s[t] = Bacc;
    __syncthreads();
    if (t < D)
        g_bB[blockIdx.x * D + t] =
            red_s[t] + red_s[32 + t] + red_s[64 + t] + red_s[96 + t];

    // ---- last finishing block: S, Bbar, score head ----
    __threadfence();
    if (t == 0) isLast = (atomicAdd(&g_cnt1, 1u) == NB - 1);
    __syncthreads();
    if (!isLast) return;

    float ls = 0.0f;
    for (int b = t; b < NB; b += T1) ls += g_bs[b];
    red_s[t] = ls;
    for (int stride = T1 / 2; stride >= 1; stride >>= 1) {
        __syncthreads();
        if (t < stride) red_s[t] += red_s[t + stride];
    }
    __syncthreads();
    const float S = red_s[0];
    if (t == 0) g_invS = 1.0f / S;
    __syncthreads();

    // Bbar: 4 lane-groups over blocks
    {
        const int d = t & (D - 1);
        const int g = t >> 5;
        float acc = 0.0f;
        for (int b = g; b < NB; b += 4) acc += g_bB[b * D + d];
        red_s[g * D + d] = acc;
    }
    __syncthreads();

    __shared__ float Bbar[D];
    __shared__ float hsh[HID];
    if (t < D)
        Bbar[t] = (red_s[t] + red_s[D + t] + red_s[2 * D + t] + red_s[3 * D + t]) / S;
    __syncthreads();
    if (t < HID) {
        float a3 = b1[t] + TPL[0] * W1[D * HID + t];   // W1 row 32 = TPL row
        #pragma unroll
        for (int dd = 0; dd < D; dd++) a3 = fmaf(Bbar[dd], W1[dd * HID + t], a3);
        hsh[t] = fmaxf(a3, 0.0f);
    }
    __syncthreads();
    if (t == 0) {
        float sc = b2[0];
        #pragma unroll
        for (int j = 0; j < HID; j++) sc = fmaf(hsh[j], W2[j], sc);
        out_score[0] = sc;
        g_cnt1 = 0;                            // reset for next graph replay
        __threadfence();
    }
}

// =====================================================================
// K2: alpha_i = exp(a_i) * invS   (pure 8 MB stream)
// =====================================================================
__global__ void __launch_bounds__(256)
k2_alpha(float* __restrict__ alpha, int n)
{
    const float inv = g_invS;
    int i = blockIdx.x * blockDim.x + threadIdx.x;
    if (i < n) alpha[i] = __expf(g_a[i]) * inv;
}

// =====================================================================
// Dummy: keeps the profiled launch (our 4th kernel) = k1 of call 2.
// =====================================================================
__global__ void k_dummy() { g_dummy = 0.0f; }

// =====================================================================
// Inputs (metadata order): H, TPL, Wv, bv, Wu, bu, Ww, bw, W1, b1, W2, b2
// Output: [score, alpha[0..N-1]]
// =====================================================================
extern "C" void kernel_launch(void* const* d_in, const int* in_sizes, int n_in,
                              void* d_out, int out_size)
{
    const float* H   = (const float*)d_in[0];
    const float* TPL = (const float*)d_in[1];
    const float* Wv  = (const float*)d_in[2];
    const float* bv  = (const float*)d_in[3];
    const float* Wu  = (const float*)d_in[4];
    const float* bu  = (const float*)d_in[5];
    const float* Ww  = (const float*)d_in[6];
    const float* bw  = (const float*)d_in[7];
    const float* W1  = (const float*)d_in[8];
    const float* b1  = (const float*)d_in[9];
    const float* W2  = (const float*)d_in[10];
    const float* b2  = (const float*)d_in[11];
    float* out = (float*)d_out;

    const int n = in_sizes[0] / D;   // 1,000,000

    k1_fused<<<NB, T1>>>((const float4*)H, n, Wv, bv, Wu, bu, Ww, bw,
                         TPL, W1, b1, W2, b2, out);
    k_dummy<<<1, 1>>>();
    k2_alpha<<<(n + 255) / 256, 256>>>(out + 1, n);
}

// round 16
// speedup vs baseline: 16.1986x; 1.2400x over previous
#include <cuda_runtime.h>

#define N_MAX   1000000
#define D       32
#define HID     16
#define NB      592          // 148 SMs x 4 blocks
#define T1      128
#define TR      128          // H-tile rows per block

// ---------------- scratch (no allocations allowed) ----------------
__device__ float g_a[N_MAX];          // per-row raw attention logits
__device__ float g_bs[NB];            // per-block sum of exp(a)
__device__ float g_bB[NB * D];        // per-block partial sum exp(a)*H
__device__ float g_invS;              // 1 / sum exp(a)
__device__ unsigned int g_cnt1;       // zero-init; reset each replay
__device__ float g_dummy;             // dummy-kernel sink

// ---------------- helpers ----------------
__device__ __forceinline__ unsigned long long pack2(float lo, float hi) {
    unsigned long long r;
    asm("mov.b64 %0, {%1, %2};" : "=l"(r) : "f"(lo), "f"(hi));
    return r;
}
__device__ __forceinline__ void unpack2(unsigned long long v, float& lo, float& hi) {
    asm("mov.b64 {%0, %1}, %2;" : "=f"(lo), "=f"(hi) : "l"(v));
}
__device__ __forceinline__ void fma2(unsigned long long& d,
                                     unsigned long long a, unsigned long long b) {
    asm("fma.rn.f32x2 %0, %1, %2, %3;" : "=l"(d) : "l"(a), "l"(b), "l"(d));
}
__device__ __forceinline__ float fast_tanh(float x) {
    float r;
    asm("tanh.approx.f32 %0, %1;" : "=f"(r) : "f"(x));
    return r;
}
__device__ __forceinline__ unsigned smem_u32(const void* p) {
    return (unsigned)__cvta_generic_to_shared(p);
}
__device__ __forceinline__ void cp16(unsigned dst, const void* src) {
    asm volatile("cp.async.cg.shared.global [%0], [%1], 16;" :: "r"(dst), "l"(src));
}
#define CP_COMMIT() asm volatile("cp.async.commit_group;" ::: "memory")
#define CP_WAIT0()  asm volatile("cp.async.wait_group 0;"  ::: "memory")

// =====================================================================
// K1: one pass over H.  HALF-WARP ROWS: smem crossbar replication was
// the measured wall (L1tex 71%: 32-lane broadcast = 4KB/row = 32 wf).
// Now lanes 0-15 process row A, lanes 16-31 row B simultaneously; each
// lane holds BOTH V and U weight columns for h=l&15 -> 16 wf/row.
//  - cp.async double-buffered 128x32 tile (proven)
//  - butterfly (8,4,2,1) stays within each 16-lane half
//  - B accumulation: lane covers columns h and h+16 of its row
// Last finishing block: S, Bbar=B/S, score head.
// =====================================================================
__global__ void __launch_bounds__(T1, 4)
k1_fused(const float4* __restrict__ H4, int n,
         const float* __restrict__ Wv, const float* __restrict__ bv,
         const float* __restrict__ Wu, const float* __restrict__ bu,
         const float* __restrict__ Ww, const float* __restrict__ bw,
         const float* __restrict__ TPL,
         const float* __restrict__ W1, const float* __restrict__ b1,
         const float* __restrict__ W2, const float* __restrict__ b2,
         float* __restrict__ out_score)
{
    __shared__ __align__(16) float4 sH[2][TR][8];  // 32 KB double buffer
    __shared__ float sWv[D * HID], sWu[D * HID];
    __shared__ float red_s[T1];
    __shared__ float red_b[T1];
    __shared__ bool  isLast;

    const int t   = threadIdx.x;
    const int w   = t >> 5;            // warp
    const int l   = t & 31;            // lane
    const int h   = l & 15;            // hidden index (both halves)
    const int sub = l >> 4;            // 0: row A, 1: row B

    for (int i = t; i < D * HID; i += T1) { sWv[i] = Wv[i]; sWu[i] = Wu[i]; }
    __syncthreads();

    // per-lane BOTH weight columns, packed d-pairs
    unsigned long long WpV[D / 2], WpU[D / 2];
    #pragma unroll
    for (int q = 0; q < D / 2; q++) {
        WpV[q] = pack2(sWv[(2 * q) * HID + h], sWv[(2 * q + 1) * HID + h]);
        WpU[q] = pack2(sWu[(2 * q) * HID + h], sWu[(2 * q + 1) * HID + h]);
    }
    const float bvh = bv[h];
    const float buh = bu[h];
    const float wwh = Ww[h];
    const float bw0 = bw[0];

    float s  = 0.0f;   // sum exp(a): lanes with h==0 only
    float Blo = 0.0f;  // column h    partial of sum e*H
    float Bhi = 0.0f;  // column h+16 partial of sum e*H

    auto stage = [&](int tile, int buf) {
        const int base = tile * TR;
        const int rows = min(TR, n - base);
        const float4* src = H4 + (size_t)base * 8;
        float4* dst = &sH[buf][0][0];
        #pragma unroll
        for (int k = 0; k < (TR * 8) / T1; k++) {
            const int f = t + k * T1;
            if (f < rows * 8) cp16(smem_u32(dst + f), src + f);
            else              dst[f] = make_float4(0.f, 0.f, 0.f, 0.f);
        }
        CP_COMMIT();
    };

    const int tile0 = blockIdx.x;
    if (tile0 * TR < n) stage(tile0, 0);
    int parity = 0;

    for (int tile = tile0; tile * TR < n; tile += NB) {
        CP_WAIT0();
        __syncthreads();                        // tile ready
        const int nxt = tile + NB;
        if (nxt * TR < n) stage(nxt, parity ^ 1);

        const int base = tile * TR;
        const int rows = min(TR, n - base);

        #pragma unroll 4
        for (int i = 0; i < 32; i += 2) {
            const int r = w * 32 + i + sub;     // half 0: even, half 1: odd

            // ---- dual matvec, 16-lane broadcast: 8 LDS.128 / 2 rows ----
            unsigned long long aV = 0ULL, aU = 0ULL;
            #pragma unroll
            for (int q = 0; q < 8; q++) {
                ulonglong2 xx = *(const ulonglong2*)&sH[parity][r][q];
                fma2(aV, xx.x, WpV[2 * q]);
                fma2(aV, xx.y, WpV[2 * q + 1]);
                fma2(aU, xx.x, WpU[2 * q]);
                fma2(aU, xx.y, WpU[2 * q + 1]);
            }
            float v0, v1, u0, u1;
            unpack2(aV, v0, v1);
            unpack2(aU, u0, u1);
            const float tv = fast_tanh(v0 + v1 + bvh);
            const float su = fmaf(0.5f, fast_tanh(0.5f * (u0 + u1 + buh)), 0.5f);
            float c = wwh * tv * su;
            // butterfly within each 16-lane half
            c += __shfl_xor_sync(0xffffffffu, c, 8);
            c += __shfl_xor_sync(0xffffffffu, c, 4);
            c += __shfl_xor_sync(0xffffffffu, c, 2);
            c += __shfl_xor_sync(0xffffffffu, c, 1);
            const float a  = c + bw0;
            const bool  ok = (r < rows);
            const float e  = ok ? __expf(a) : 0.0f;
            if (ok && h == 0) g_a[base + r] = a;
            if (h == 0) s += e;
            // fused B: lane covers columns h and h+16 of its row
            const float* rowf = (const float*)&sH[parity][r][0];
            Blo = fmaf(e, rowf[h],      Blo);
            Bhi = fmaf(e, rowf[h + 16], Bhi);
        }
        parity ^= 1;
        __syncthreads();                        // buffer reuse guard
    }

    // ---- block reduction: s ----
    red_s[t] = s;
    for (int stride = T1 / 2; stride >= 1; stride >>= 1) {
        __syncthreads();
        if (t < stride) red_s[t] += red_s[t + stride];
    }
    __syncthreads();
    if (t == 0) g_bs[blockIdx.x] = red_s[0];
    __syncthreads();

    // ---- block reduction: B ----
    // column d<16: red_s entries with (l&15)==d; d>=16: red_b entries
    red_s[t] = Blo;
    red_b[t] = Bhi;
    __syncthreads();
    if (t < D) {
        float acc = 0.0f;
        if (t < 16) {
            #pragma unroll
            for (int ww2 = 0; ww2 < 4; ww2++)
                acc += red_s[ww2 * 32 + t] + red_s[ww2 * 32 + 16 + t];
        } else {
            const int d16 = t - 16;
            #pragma unroll
            for (int ww2 = 0; ww2 < 4; ww2++)
                acc += red_b[ww2 * 32 + d16] + red_b[ww2 * 32 + 16 + d16];
        }
        g_bB[blockIdx.x * D + t] = acc;
    }

    // ---- last finishing block: S, Bbar, score head ----
    __threadfence();
    if (t == 0) isLast = (atomicAdd(&g_cnt1, 1u) == NB - 1);
    __syncthreads();
    if (!isLast) return;

    float ls = 0.0f;
    for (int b = t; b < NB; b += T1) ls += g_bs[b];
    red_s[t] = ls;
    for (int stride = T1 / 2; stride >= 1; stride >>= 1) {
        __syncthreads();
        if (t < stride) red_s[t] += red_s[t + stride];
    }
    __syncthreads();
    const float S = red_s[0];
    if (t == 0) g_invS = 1.0f / S;
    __syncthreads();

    // Bbar: 4 lane-groups over blocks
    {
        const int d = t & (D - 1);
        const int g = t >> 5;
        float acc = 0.0f;
        for (int b = g; b < NB; b += 4) acc += g_bB[b * D + d];
        red_s[g * D + d] = acc;
    }
    __syncthreads();

    __shared__ float Bbar[D];
    __shared__ float hsh[HID];
    if (t < D)
        Bbar[t] = (red_s[t] + red_s[D + t] + red_s[2 * D + t] + red_s[3 * D + t]) / S;
    __syncthreads();
    if (t < HID) {
        float a3 = b1[t] + TPL[0] * W1[D * HID + t];   // W1 row 32 = TPL row
        #pragma unroll
        for (int dd = 0; dd < D; dd++) a3 = fmaf(Bbar[dd], W1[dd * HID + t], a3);
        hsh[t] = fmaxf(a3, 0.0f);
    }
    __syncthreads();
    if (t == 0) {
        float sc = b2[0];
        #pragma unroll
        for (int j = 0; j < HID; j++) sc = fmaf(hsh[j], W2[j], sc);
        out_score[0] = sc;
        g_cnt1 = 0;                            // reset for next graph replay
        __threadfence();
    }
}

// =====================================================================
// K2: alpha_i = exp(a_i) * invS   (pure 8 MB stream)
// =====================================================================
__global__ void __launch_bounds__(256)
k2_alpha(float* __restrict__ alpha, int n)
{
    const float inv = g_invS;
    int i = blockIdx.x * blockDim.x + threadIdx.x;
    if (i < n) alpha[i] = __expf(g_a[i]) * inv;
}

// =====================================================================
// Dummy: keeps the profiled launch (our 4th kernel) = k1 of call 2.
// =====================================================================
__global__ void k_dummy() { g_dummy = 0.0f; }

// =====================================================================
// Inputs (metadata order): H, TPL, Wv, bv, Wu, bu, Ww, bw, W1, b1, W2, b2
// Output: [score, alpha[0..N-1]]
// =====================================================================
extern "C" void kernel_launch(void* const* d_in, const int* in_sizes, int n_in,
                              void* d_out, int out_size)
{
    const float* H   = (const float*)d_in[0];
    const float* TPL = (const float*)d_in[1];
    const float* Wv  = (const float*)d_in[2];
    const float* bv  = (const float*)d_in[3];
    const float* Wu  = (const float*)d_in[4];
    const float* bu  = (const float*)d_in[5];
    const float* Ww  = (const float*)d_in[6];
    const float* bw  = (const float*)d_in[7];
    const float* W1  = (const float*)d_in[8];
    const float* b1  = (const float*)d_in[9];
    const float* W2  = (const float*)d_in[10];
    const float* b2  = (const float*)d_in[11];
    float* out = (float*)d_out;

    const int n = in_sizes[0] / D;   // 1,000,000

    k1_fused<<<NB, T1>>>((const float4*)H, n, Wv, bv, Wu, bu, Ww, bw,
                         TPL, W1, b1, W2, b2, out);
    k_dummy<<<1, 1>>>();
    k2_alpha<<<(n + 255) / 256, 256>>>(out + 1, n);
}